// round 5
// baseline (speedup 1.0000x reference)
#include <cuda_runtime.h>
#include <cuda_bf16.h>

#define NROWS 4096
#define NF    256
#define NH    4
#define NB    128           // blocks (<= 148 SMs -> spin barrier is deadlock-free)
#define TPB   512
#define RPB   (NROWS / NB)  // 32 rows per block

// Scratch (__device__ globals per allocation-free rule)
__device__ float4  g_dpart[NB];          // per-block d[h] partials
__device__ float   g_cpart[NF * NB];     // TRANSPOSED [f][b] head-collapsed partials
__device__ unsigned g_cnt1, g_cnt2;      // monotonic epoch counters (graph-replay safe)

__device__ __forceinline__ void grid_sync(unsigned* cnt) {
    __threadfence();
    __syncthreads();
    if (threadIdx.x == 0) {
        unsigned old = atomicAdd(cnt, 1u);
        unsigned target = (old / NB + 1u) * NB;   // end of THIS launch's epoch
        while (*(volatile unsigned*)cnt < target) { }
        __threadfence();
    }
    __syncthreads();
}

__global__ void __launch_bounds__(TPB, 1)
fused_mha(const float* __restrict__ x, const float* __restrict__ W,
          float* __restrict__ out)
{
    __shared__ float4 xs[RPB * (NF / 4)];   // 32 KB: this block's 32 rows of x
    __shared__ float4 w2s[NH][NF / 4];      // 4 KB:  W2 = W[:, 256:512]
    __shared__ float4 es4[RPB];             // exp(scores) per row
    __shared__ float  sinv[NH];             // 1 / (H * d[h])
    __shared__ float  chalf[NF];            // cross-half t merge
    __shared__ float  sfin[NH];             // final 4 column values (this block's group)

    const int tid  = threadIdx.x;
    const int lane = tid & 31, warp = tid >> 5;
    const int b    = blockIdx.x;
    const int rowbase = b * RPB;

    // ---- load W2 + x tile (x read from DRAM exactly once) ------------------
    if (tid < NH * (NF / 4)) {
        int h = tid >> 6, k = tid & 63;
        w2s[h][k] = reinterpret_cast<const float4*>(W + h * 2 * NF + NF)[k];
    }
    const float4* xg = reinterpret_cast<const float4*>(x) + (size_t)rowbase * (NF / 4);
    #pragma unroll
    for (int i = 0; i < (RPB * NF / 4) / TPB; ++i)   // 4 float4 loads/thread
        xs[tid + i * TPB] = xg[tid + i * TPB];
    __syncthreads();

    // ---- Phase 1a: scores + exp, 2 rows per warp (16 warps) ----------------
    // (no max-subtraction: scores ~ N(0, 0.16); softmax is shift-invariant,
    //  so this matches the reference)
    #pragma unroll
    for (int r = warp; r < RPB; r += 16) {
        float a0 = 0.f, a1 = 0.f, a2 = 0.f, a3 = 0.f;
        #pragma unroll
        for (int t = 0; t < 2; ++t) {
            const int k4 = lane + t * 32;
            const float4 xv = xs[r * (NF / 4) + k4];
            float4 w;
            w = w2s[0][k4]; a0 += xv.x*w.x + xv.y*w.y + xv.z*w.z + xv.w*w.w;
            w = w2s[1][k4]; a1 += xv.x*w.x + xv.y*w.y + xv.z*w.z + xv.w*w.w;
            w = w2s[2][k4]; a2 += xv.x*w.x + xv.y*w.y + xv.z*w.z + xv.w*w.w;
            w = w2s[3][k4]; a3 += xv.x*w.x + xv.y*w.y + xv.z*w.z + xv.w*w.w;
        }
        #pragma unroll
        for (int o = 16; o; o >>= 1) {
            a0 += __shfl_xor_sync(0xffffffffu, a0, o);
            a1 += __shfl_xor_sync(0xffffffffu, a1, o);
            a2 += __shfl_xor_sync(0xffffffffu, a2, o);
            a3 += __shfl_xor_sync(0xffffffffu, a3, o);
        }
        if (lane == 0)
            es4[r] = make_float4(expf(a0), expf(a1), expf(a2), expf(a3));
    }
    __syncthreads();

    // ---- Phase 1b: d[h] partial + register t[h, f] (split over 2 halves) ---
    if (tid < NH) {
        float s = 0.f;
        #pragma unroll
        for (int r = 0; r < RPB; ++r) s += ((const float*)&es4[r])[tid];
        ((float*)&g_dpart[b])[tid] = s;
    }
    const int f    = tid & (NF - 1);
    const int half = tid >> 8;            // 0 or 1
    const int rb   = half * (RPB / 2);    // 16 rows per half
    float t0 = 0.f, t1 = 0.f, t2 = 0.f, t3 = 0.f;
    {
        const float* xsf = (const float*)xs;
        #pragma unroll
        for (int r = 0; r < RPB / 2; ++r) {
            const float4 e = es4[rb + r];               // smem broadcast
            const float xv = xsf[(rb + r) * NF + f];    // conflict-free
            t0 += e.x * xv; t1 += e.y * xv;
            t2 += e.z * xv; t3 += e.w * xv;
        }
    }

    grid_sync(&g_cnt1);

    // ---- Phase 2: global inv[h], head-collapse, write transposed partial ---
    if (warp == 0) {
        float4 d0 = g_dpart[lane];
        float4 d1 = g_dpart[lane + 32];
        float4 d2 = g_dpart[lane + 64];
        float4 d3 = g_dpart[lane + 96];
        float s0 = (d0.x + d1.x) + (d2.x + d3.x);
        float s1 = (d0.y + d1.y) + (d2.y + d3.y);
        float s2 = (d0.z + d1.z) + (d2.z + d3.z);
        float s3 = (d0.w + d1.w) + (d2.w + d3.w);
        #pragma unroll
        for (int o = 16; o; o >>= 1) {
            s0 += __shfl_xor_sync(0xffffffffu, s0, o);
            s1 += __shfl_xor_sync(0xffffffffu, s1, o);
            s2 += __shfl_xor_sync(0xffffffffu, s2, o);
            s3 += __shfl_xor_sync(0xffffffffu, s3, o);
        }
        if (lane == 0) {
            sinv[0] = 1.f / ((float)NH * s0);
            sinv[1] = 1.f / ((float)NH * s1);
            sinv[2] = 1.f / ((float)NH * s2);
            sinv[3] = 1.f / ((float)NH * s3);
        }
    }
    __syncthreads();

    float c = sinv[0]*t0 + sinv[1]*t1 + sinv[2]*t2 + sinv[3]*t3;
    if (half) chalf[f] = c;
    __syncthreads();
    if (!half) g_cpart[f * NB + b] = c + chalf[f];   // transposed: [f][b]

    grid_sync(&g_cnt2);

    // ---- Phase 3 (NO further sync): block b owns column-group g = b>>1 -----
    // and row-half b&1. Reduce its 4 columns over all blocks (coalesced reads),
    // leaky_relu, then write them directly to its 2048 output rows.
    const int g = b >> 1;                 // float4 column group 0..63
    if (warp < 4) {                       // warp w reduces column 4g + w
        const float* cp = g_cpart + (4 * g + warp) * NB;
        float s = (cp[lane] + cp[lane + 32]) + (cp[lane + 64] + cp[lane + 96]);
        #pragma unroll
        for (int o = 16; o; o >>= 1) s += __shfl_xor_sync(0xffffffffu, s, o);
        if (lane == 0) sfin[warp] = (s > 0.f) ? s : 0.2f * s;
    }
    __syncthreads();
    const float4 v = make_float4(sfin[0], sfin[1], sfin[2], sfin[3]);

    float4* og = reinterpret_cast<float4*>(out);
    const int rowstart = (b & 1) * (NROWS / 2);      // 2048 rows
    #pragma unroll
    for (int i = 0; i < (NROWS / 2) / TPB; ++i) {    // 4 stores/thread
        const int row = rowstart + tid + i * TPB;
        og[(size_t)row * (NF / 4) + g] = v;
    }
}

extern "C" void kernel_launch(void* const* d_in, const int* in_sizes, int n_in,
                              void* d_out, int out_size) {
    const float* x = (const float*)d_in[0];   // (4096, 256) f32
    const float* W = (const float*)d_in[1];   // (4, 512) f32; only W[:,256:] matters
    // d_in[2] = b: cancels inside softmax, mathematically irrelevant
    float* out = (float*)d_out;               // (4096, 256) f32

    fused_mha<<<NB, TPB>>>(x, W, out);
}